// round 15
// baseline (speedup 1.0000x reference)
#include <cuda_runtime.h>
#include <cuda_fp16.h>
#include <cstdint>

#define BB 4096
#define TT 512
#define IND 5
#define E 30
#define NH 3
#define HD 10
#define KSPLIT 32
#define KTILE 128   // 4096 / KSPLIT
#define RQ 2        // q rows per thread in attention
#define ATHR 256    // attention block size
#define CH 16       // LSTM steps per prefetched x chunk

typedef unsigned long long u64;

// ---------------- scratch (device globals; no allocations allowed) ----------
__device__ float g_hn[BB * E];
__device__ float g_q[BB * E];
__device__ float g_k[BB * E];
__device__ float g_v[BB * E];
__device__ float g_psum[BB * NH * KSPLIT];            // [q][h][ksp]
__device__ float g_pacc[BB * NH * KSPLIT * HD];       // [q][h][ksp][d]

// ---------------- f32x2 helpers (attention kernel) ---------------------------
__device__ __forceinline__ u64 pack2(float lo, float hi) {
    u64 r; asm("mov.b64 %0, {%1, %2};" : "=l"(r) : "f"(lo), "f"(hi)); return r;
}
__device__ __forceinline__ u64 bcast2(float v) {
    u64 r; asm("mov.b64 %0, {%1, %1};" : "=l"(r) : "f"(v)); return r;
}
__device__ __forceinline__ void unpack2(u64 p, float& lo, float& hi) {
    asm("mov.b64 {%0, %1}, %2;" : "=f"(lo), "=f"(hi) : "l"(p));
}
__device__ __forceinline__ u64 ffma2(u64 a, u64 b, u64 c) {
    u64 d; asm("fma.rn.f32x2 %0, %1, %2, %3;" : "=l"(d) : "l"(a), "l"(b), "l"(c));
    return d;
}

// ---------------- activation helpers -----------------------------------------
__device__ __forceinline__ float tanh_fast(float x) {
    float y; asm("tanh.approx.f32 %0, %1;" : "=f"(y) : "f"(x)); return y;
}
__device__ __forceinline__ __half2 tanh2_fast(__half2 x) {
    __half2 y;
    asm("tanh.approx.f16x2 %0, %1;"
        : "=r"(*reinterpret_cast<uint32_t*>(&y))
        : "r"(*reinterpret_cast<const uint32_t*>(&x)));
    return y;
}
__device__ __forceinline__ float warp_sum(float v) {
    #pragma unroll
    for (int o = 16; o > 0; o >>= 1) v += __shfl_xor_sync(0xffffffffu, v, o);
    return v;
}

// ---------------- kernel 1: LSTM (gate-paired HFMA2) + fused QKV tail ---------
// Activation pre-scales folded into weights. h staged as duplicated half2 in
// smem; same-warp STS->LDS ordering is guaranteed by the in-order LSU (no
// divergence here), so the per-step barrier is a compiler-only fence.
__global__ __launch_bounds__(128, 4) void lstm_kernel(
    const float* __restrict__ input, const float* __restrict__ w_ih,
    const float* __restrict__ w_hh, const float* __restrict__ b_ih,
    const float* __restrict__ b_hh, const float* __restrict__ ipw,
    const float* __restrict__ ipb)
{
    __shared__ __align__(16) __half2 hbuf[4][2][32];      // (h_j,h_j) per lane
    __shared__ __align__(16) __half2 xs[4][2][CH][8];     // comps 0-4 x, 5=(1,1)

    int wl   = threadIdx.x >> 5;
    int warp = blockIdx.x * 4 + wl;
    int lane = threadIdx.x & 31;
    bool act = lane < E;
    int li = act ? lane : 0;

    // stationary gate-paired weights, activation scales folded in
    __half2 whhIF[E], whhGO[E];
    __half2 wxIF[6], wxGO[6];
    #pragma unroll
    for (int j = 0; j < E; j++) {
        whhIF[j] = __halves2half2(
            __float2half_rn(0.5f * __ldg(w_hh + (0 * E + li) * E + j)),
            __float2half_rn(0.5f * __ldg(w_hh + (1 * E + li) * E + j)));
        whhGO[j] = __halves2half2(
            __float2half_rn(__ldg(w_hh + (2 * E + li) * E + j)),
            __float2half_rn(0.5f * __ldg(w_hh + (3 * E + li) * E + j)));
    }
    #pragma unroll
    for (int k = 0; k < IND; k++) {
        wxIF[k] = __halves2half2(
            __float2half_rn(0.5f * __ldg(w_ih + (0 * E + li) * IND + k)),
            __float2half_rn(0.5f * __ldg(w_ih + (1 * E + li) * IND + k)));
        wxGO[k] = __halves2half2(
            __float2half_rn(__ldg(w_ih + (2 * E + li) * IND + k)),
            __float2half_rn(0.5f * __ldg(w_ih + (3 * E + li) * IND + k)));
    }
    wxIF[5] = __halves2half2(
        __float2half_rn(0.5f * (__ldg(b_ih + 0 * E + li) + __ldg(b_hh + 0 * E + li))),
        __float2half_rn(0.5f * (__ldg(b_ih + 1 * E + li) + __ldg(b_hh + 1 * E + li))));
    wxGO[5] = __halves2half2(
        __float2half_rn(__ldg(b_ih + 2 * E + li) + __ldg(b_hh + 2 * E + li)),
        __float2half_rn(0.5f * (__ldg(b_ih + 3 * E + li) + __ldg(b_hh + 3 * E + li))));

    const float* xbase = input + (size_t)warp * TT * IND;

    if (lane < CH) {
        __half2 one2 = __floats2half2_rn(1.0f, 1.0f);
        xs[wl][0][lane][5] = one2;
        xs[wl][1][lane][5] = one2;
    }

    float4 pf = make_float4(0.f, 0.f, 0.f, 0.f);
    bool ldr = lane < 20;
    int s0 = 0, c0 = 0;
    if (ldr) { int g0 = lane * 4; s0 = g0 / 5; c0 = g0 - s0 * 5; }

    auto stage_chunk = [&](int buf, float4 v) {
        if (ldr) {
            int s = s0, cc = c0;
            float vv[4] = {v.x, v.y, v.z, v.w};
            #pragma unroll
            for (int j = 0; j < 4; j++) {
                xs[wl][buf][s][cc] = __float2half2_rn(vv[j]);   // duplicated
                if (++cc == 5) { cc = 0; s++; }
            }
        }
    };

    if (ldr) pf = *(const float4*)(xbase + lane * 4);
    stage_chunk(0, pf);
    __syncwarp();
    if (ldr) pf = *(const float4*)(xbase + CH * IND + lane * 4);

    float h = 0.0f, c = 0.0f;
    const __half2 aff_m = __floats2half2_rn(1.0f, 0.5f);   // (gg scale, og scale)
    const __half2 aff_b = __floats2half2_rn(0.0f, 0.5f);
    const __half2 half2c = __floats2half2_rn(0.5f, 0.5f);

    for (int ch = 0; ch < TT / CH; ch++) {
        #pragma unroll
        for (int s = 0; s < CH; s++) {
            __half2* hb = hbuf[wl][s & 1];
            hb[lane] = __float2half2_rn(h);
            asm volatile("" ::: "memory");   // compiler fence; LSU orders STS->LDS

            uint4 xv[2];
            xv[0] = *(const uint4*)&xs[wl][ch & 1][s][0];
            xv[1] = *(const uint4*)&xs[wl][ch & 1][s][4];
            const __half2* xm = reinterpret_cast<const __half2*>(xv);

            __half2 aIF0, aIF1, aGO0, aGO1;
            aIF0 = __hmul2(wxIF[0], xm[0]);
            aIF1 = __hmul2(wxIF[1], xm[1]);
            aGO0 = __hmul2(wxGO[0], xm[0]);
            aGO1 = __hmul2(wxGO[1], xm[1]);
            #pragma unroll
            for (int k = 2; k < 6; k += 2) {
                aIF0 = __hfma2(wxIF[k],     xm[k],     aIF0);
                aIF1 = __hfma2(wxIF[k + 1], xm[k + 1], aIF1);
                aGO0 = __hfma2(wxGO[k],     xm[k],     aGO0);
                aGO1 = __hfma2(wxGO[k + 1], xm[k + 1], aGO1);
            }

            // h dot: consume one 16B quarter at a time (low reg pressure)
            #pragma unroll
            for (int q = 0; q < 8; q++) {
                uint4 hv = ((const uint4*)hb)[q];
                const __half2* hm = reinterpret_cast<const __half2*>(&hv);
                #pragma unroll
                for (int j = 0; j < 4; j += 2) {
                    int idx = q * 4 + j;
                    if (idx < E) {
                        aIF0 = __hfma2(whhIF[idx],     hm[j],     aIF0);
                        aIF1 = __hfma2(whhIF[idx + 1], hm[j + 1], aIF1);
                        aGO0 = __hfma2(whhGO[idx],     hm[j],     aGO0);
                        aGO1 = __hfma2(whhGO[idx + 1], hm[j + 1], aGO1);
                    }
                }
            }

            __half2 aIF = __hadd2(aIF0, aIF1);
            __half2 aGO = __hadd2(aGO0, aGO1);

            __half2 tIF = tanh2_fast(aIF);   // (tanh(i/2), tanh(f/2))
            __half2 tGO = tanh2_fast(aGO);   // (tanh(g),   tanh(o/2))

            // affine in half2: sigmoid pair = 0.5*t+0.5; (gg,og) = (g, 0.5*t+0.5)
            __half2 sIF = __hfma2(tIF, half2c, half2c);      // (ig, fg)
            __half2 sGO = __hfma2(tGO, aff_m, aff_b);        // (gg, og)

            float ig = __low2float(sIF);
            float fg = __high2float(sIF);
            float gg = __low2float(sGO);
            float og = __high2float(sGO);
            c = fmaf(fg, c, ig * gg);
            h = og * tanh_fast(c);
        }
        if (ch + 1 < TT / CH) {
            stage_chunk((ch + 1) & 1, pf);
            __syncwarp();
            if (ch + 2 < TT / CH && ldr)
                pf = *(const float4*)(xbase + (ch + 2) * CH * IND + lane * 4);
        }
    }

    // ---- fused QKV tail ----
    float aq = __ldg(ipb + 0 * E + li);
    float ak = __ldg(ipb + 1 * E + li);
    float av = __ldg(ipb + 2 * E + li);
    #pragma unroll
    for (int j = 0; j < E; j++) {
        float hj = __shfl_sync(0xffffffffu, h, j);
        float cj = __shfl_sync(0xffffffffu, c, j);
        aq = fmaf(__ldg(ipw + (0 * E + li) * E + j), hj, aq);
        ak = fmaf(__ldg(ipw + (1 * E + li) * E + j), cj, ak);
        av = fmaf(__ldg(ipw + (2 * E + li) * E + j), cj, av);
    }
    if (act) {
        g_hn[(size_t)warp * E + lane] = h;
        g_q[(size_t)warp * E + lane] = aq;
        g_k[(size_t)warp * E + lane] = ak;
        g_v[(size_t)warp * E + lane] = av;
    }
}

// ---------------- kernel 2: attention partials (flash-style, no-max) ----------
// KSPLIT=32 -> 768 CTAs (~5.2/SM), 10KB smem each.
__global__ __launch_bounds__(ATHR) void attn_kernel()
{
    __shared__ u64 ks2[KTILE * 5];
    __shared__ u64 vs2[KTILE * 5];
    int h   = blockIdx.z;
    int ksp = blockIdx.y;
    int qc  = blockIdx.x;
    int tid = threadIdx.x;
    int k0  = ksp * KTILE;

    for (int i = tid; i < KTILE * 5; i += ATHR) {
        int m = i / 5, p = i - m * 5;
        const float2* kp = (const float2*)(g_k + (size_t)(k0 + m) * E + h * HD) + p;
        const float2* vp = (const float2*)(g_v + (size_t)(k0 + m) * E + h * HD) + p;
        float2 kv = *kp; float2 vv = *vp;
        ks2[i] = pack2(kv.x, kv.y);
        vs2[i] = pack2(vv.x, vv.y);
    }
    __syncthreads();

    int q0 = qc * (ATHR * RQ) + tid * RQ;
    const float QSC = 0.3162277660168379f * 1.4426950408889634f; // rsqrt(HD)*log2e

    u64 qp[RQ][5], accp[RQ][5];
    float s[RQ];
    #pragma unroll
    for (int r = 0; r < RQ; r++) {
        s[r] = 0.0f;
        #pragma unroll
        for (int p = 0; p < 5; p++) {
            float2 t = *((const float2*)(g_q + (size_t)(q0 + r) * E + h * HD) + p);
            qp[r][p] = pack2(t.x * QSC, t.y * QSC);
            accp[r][p] = pack2(0.0f, 0.0f);
        }
    }

    for (int m = 0; m < KTILE; m++) {
        u64 kk[5], vv[5];
        #pragma unroll
        for (int p = 0; p < 5; p++) { kk[p] = ks2[m * 5 + p]; vv[p] = vs2[m * 5 + p]; }
        #pragma unroll
        for (int r = 0; r < RQ; r++) {
            u64 d2 = pack2(0.0f, 0.0f);
            #pragma unroll
            for (int p = 0; p < 5; p++) d2 = ffma2(qp[r][p], kk[p], d2);
            float lo, hi; unpack2(d2, lo, hi);
            float pr = exp2f(lo + hi);
            s[r] += pr;
            u64 p2 = bcast2(pr);
            #pragma unroll
            for (int p = 0; p < 5; p++) accp[r][p] = ffma2(p2, vv[p], accp[r][p]);
        }
    }

    #pragma unroll
    for (int r = 0; r < RQ; r++) {
        int base = (q0 + r) * (NH * KSPLIT) + h * KSPLIT + ksp;
        g_psum[base] = s[r];
        #pragma unroll
        for (int p = 0; p < 5; p++) {
            float lo, hi; unpack2(accp[r][p], lo, hi);
            g_pacc[(size_t)base * HD + 2 * p]     = lo;
            g_pacc[(size_t)base * HD + 2 * p + 1] = hi;
        }
    }
}

// ---------------- kernel 3: combine + out_proj + LN + MLP + LN + head --------
__global__ __launch_bounds__(256) void epi_kernel(
    const float* __restrict__ opw, const float* __restrict__ opb,
    const float* __restrict__ f1w, const float* __restrict__ f1b,
    const float* __restrict__ f2w, const float* __restrict__ f2b,
    const float* __restrict__ lng, const float* __restrict__ lnb,
    const float* __restrict__ ow,  const float* __restrict__ ob,
    float* __restrict__ out)
{
    int warp = (blockIdx.x * blockDim.x + threadIdx.x) >> 5;
    int lane = threadIdx.x & 31;
    bool act = lane < E;
    int li = act ? lane : 0;
    int hh = li / HD, dd = li - hh * HD;

    // combine split-softmax partials ([q][h][ksp][d]: contiguous per row)
    float num = 0.0f, den = 0.0f;
    #pragma unroll
    for (int ksp = 0; ksp < KSPLIT; ksp++) {
        int base = warp * (NH * KSPLIT) + hh * KSPLIT + ksp;
        num += g_pacc[(size_t)base * HD + dd];
        den += g_psum[base];
    }
    float ctx = __fdividef(num, den);

    // out_proj
    float ao = __ldg(opb + li);
    #pragma unroll
    for (int j = 0; j < E; j++) {
        float cj = __shfl_sync(0xffffffffu, ctx, j);
        ao = fmaf(__ldg(opw + li * E + j), cj, ao);
    }
    float r1 = ao + g_hn[(size_t)warp * E + li];

    // LN1
    float lg = __ldg(lng + li), lb = __ldg(lnb + li);
    float mu = warp_sum(act ? r1 : 0.0f) * (1.0f / E);
    float dv = act ? (r1 - mu) : 0.0f;
    float var = warp_sum(dv * dv) * (1.0f / E);
    float x1 = fmaf(dv * rsqrtf(var + 1e-5f), lg, lb);
    if (!act) x1 = 0.0f;

    // fc1 + exact GELU
    float y = __ldg(f1b + li);
    #pragma unroll
    for (int j = 0; j < E; j++) {
        float xj = __shfl_sync(0xffffffffu, x1, j);
        y = fmaf(__ldg(f1w + li * E + j), xj, y);
    }
    float gy = 0.5f * y * (1.0f + erff(y * 0.7071067811865475f));

    // fc2
    float z = __ldg(f2b + li);
    #pragma unroll
    for (int j = 0; j < E; j++) {
        float gj = __shfl_sync(0xffffffffu, gy, j);
        z = fmaf(__ldg(f2w + li * E + j), gj, z);
    }
    float r2 = x1 + z;

    // LN2
    float mu2 = warp_sum(act ? r2 : 0.0f) * (1.0f / E);
    float dv2 = act ? (r2 - mu2) : 0.0f;
    float var2 = warp_sum(dv2 * dv2) * (1.0f / E);
    float x2 = fmaf(dv2 * rsqrtf(var2 + 1e-5f), lg, lb);
    if (!act) x2 = 0.0f;

    // final head [E -> 3]
    float o0 = __ldg(ob + 0), o1 = __ldg(ob + 1), o2 = __ldg(ob + 2);
    #pragma unroll
    for (int j = 0; j < E; j++) {
        float xj = __shfl_sync(0xffffffffu, x2, j);
        o0 = fmaf(__ldg(ow + 0 * E + j), xj, o0);
        o1 = fmaf(__ldg(ow + 1 * E + j), xj, o1);
        o2 = fmaf(__ldg(ow + 2 * E + j), xj, o2);
    }
    if (lane == 0) {
        out[(size_t)warp * 3 + 0] = o0;
        out[(size_t)warp * 3 + 1] = o1;
        out[(size_t)warp * 3 + 2] = o2;
    }
}

// ---------------- launch ------------------------------------------------------
extern "C" void kernel_launch(void* const* d_in, const int* in_sizes, int n_in,
                              void* d_out, int out_size)
{
    const float* input = (const float*)d_in[0];   // [4096,512,5]
    const float* w_ih  = (const float*)d_in[1];   // [120,5]
    const float* w_hh  = (const float*)d_in[2];   // [120,30]
    const float* b_ih  = (const float*)d_in[3];   // [120]
    const float* b_hh  = (const float*)d_in[4];   // [120]
    const float* ipw   = (const float*)d_in[5];   // [90,30]
    const float* ipb   = (const float*)d_in[6];   // [90]
    const float* opw   = (const float*)d_in[7];   // [30,30]
    const float* opb   = (const float*)d_in[8];   // [30]
    const float* f1w   = (const float*)d_in[9];   // [30,30]
    const float* f1b   = (const float*)d_in[10];  // [30]
    const float* f2w   = (const float*)d_in[11];  // [30,30]
    const float* f2b   = (const float*)d_in[12];  // [30]
    const float* lng   = (const float*)d_in[13];  // [30]
    const float* lnb   = (const float*)d_in[14];  // [30]
    const float* ow    = (const float*)d_in[15];  // [3,30]
    const float* ob    = (const float*)d_in[16];  // [3]
    float* out = (float*)d_out;

    lstm_kernel<<<BB / 4, 128>>>(input, w_ih, w_hh, b_ih, b_hh, ipw, ipb);
    attn_kernel<<<dim3(BB / (ATHR * RQ), KSPLIT, NH), ATHR>>>();
    epi_kernel<<<BB / 8, 256>>>(opw, opb, f1w, f1b, f2w, f2b, lng, lnb, ow, ob, out);
}

// round 17
// speedup vs baseline: 1.0321x; 1.0321x over previous
#include <cuda_runtime.h>
#include <cuda_fp16.h>
#include <cstdint>

#define BB 4096
#define TT 512
#define IND 5
#define E 30
#define NH 3
#define HD 10
#define KSPLIT 16
#define KTILE 256   // 4096 / KSPLIT
#define RQ 2        // q rows per thread in attention
#define ATHR 256    // attention block size
#define CH 16       // LSTM steps per prefetched x chunk
#define KST 6       // padded u64 stride per k/v row in attn smem (48B, 16B-aligned)

typedef unsigned long long u64;

// ---------------- scratch (device globals; no allocations allowed) ----------
__device__ float g_hn[BB * E];
__device__ float g_q[BB * E];
__device__ float g_k[BB * E];
__device__ float g_v[BB * E];
__device__ float g_psum[BB * NH * KSPLIT];            // [q][h][ksp]
__device__ float g_pacc[BB * NH * KSPLIT * HD];       // [q][h][ksp][d]

// ---------------- f32x2 helpers (attention kernel) ---------------------------
__device__ __forceinline__ u64 pack2(float lo, float hi) {
    u64 r; asm("mov.b64 %0, {%1, %2};" : "=l"(r) : "f"(lo), "f"(hi)); return r;
}
__device__ __forceinline__ u64 bcast2(float v) {
    u64 r; asm("mov.b64 %0, {%1, %1};" : "=l"(r) : "f"(v)); return r;
}
__device__ __forceinline__ void unpack2(u64 p, float& lo, float& hi) {
    asm("mov.b64 {%0, %1}, %2;" : "=f"(lo), "=f"(hi) : "l"(p));
}
__device__ __forceinline__ u64 ffma2(u64 a, u64 b, u64 c) {
    u64 d; asm("fma.rn.f32x2 %0, %1, %2, %3;" : "=l"(d) : "l"(a), "l"(b), "l"(c));
    return d;
}

// ---------------- activation helpers -----------------------------------------
__device__ __forceinline__ float tanh_fast(float x) {
    float y; asm("tanh.approx.f32 %0, %1;" : "=f"(y) : "f"(x)); return y;
}
__device__ __forceinline__ __half2 tanh2_fast(__half2 x) {
    __half2 y;
    asm("tanh.approx.f16x2 %0, %1;"
        : "=r"(*reinterpret_cast<uint32_t*>(&y))
        : "r"(*reinterpret_cast<const uint32_t*>(&x)));
    return y;
}
__device__ __forceinline__ float warp_sum(float v) {
    #pragma unroll
    for (int o = 16; o > 0; o >>= 1) v += __shfl_xor_sync(0xffffffffu, v, o);
    return v;
}

// ---------------- kernel 1: LSTM (gate-paired HFMA2) + fused QKV tail ---------
// Activation pre-scales folded into weights. Biases init the second
// accumulator chain (no constant-one MAC slot). c, h fp32.
__global__ __launch_bounds__(128, 4) void lstm_kernel(
    const float* __restrict__ input, const float* __restrict__ w_ih,
    const float* __restrict__ w_hh, const float* __restrict__ b_ih,
    const float* __restrict__ b_hh, const float* __restrict__ ipw,
    const float* __restrict__ ipb)
{
    __shared__ __align__(16) __half2 hbuf[4][2][32];      // (h_j,h_j) per lane
    __shared__ __align__(16) __half2 xs[4][2][CH][8];     // comps 0-4 x (5..7 pad)

    int wl   = threadIdx.x >> 5;
    int warp = blockIdx.x * 4 + wl;
    int lane = threadIdx.x & 31;
    bool act = lane < E;
    int li = act ? lane : 0;

    // stationary gate-paired weights, activation scales folded in
    __half2 whhIF[E], whhGO[E];
    __half2 wxIF[IND], wxGO[IND], bIF2, bGO2;
    #pragma unroll
    for (int j = 0; j < E; j++) {
        whhIF[j] = __halves2half2(
            __float2half_rn(0.5f * __ldg(w_hh + (0 * E + li) * E + j)),
            __float2half_rn(0.5f * __ldg(w_hh + (1 * E + li) * E + j)));
        whhGO[j] = __halves2half2(
            __float2half_rn(__ldg(w_hh + (2 * E + li) * E + j)),
            __float2half_rn(0.5f * __ldg(w_hh + (3 * E + li) * E + j)));
    }
    #pragma unroll
    for (int k = 0; k < IND; k++) {
        wxIF[k] = __halves2half2(
            __float2half_rn(0.5f * __ldg(w_ih + (0 * E + li) * IND + k)),
            __float2half_rn(0.5f * __ldg(w_ih + (1 * E + li) * IND + k)));
        wxGO[k] = __halves2half2(
            __float2half_rn(__ldg(w_ih + (2 * E + li) * IND + k)),
            __float2half_rn(0.5f * __ldg(w_ih + (3 * E + li) * IND + k)));
    }
    bIF2 = __halves2half2(
        __float2half_rn(0.5f * (__ldg(b_ih + 0 * E + li) + __ldg(b_hh + 0 * E + li))),
        __float2half_rn(0.5f * (__ldg(b_ih + 1 * E + li) + __ldg(b_hh + 1 * E + li))));
    bGO2 = __halves2half2(
        __float2half_rn(__ldg(b_ih + 2 * E + li) + __ldg(b_hh + 2 * E + li)),
        __float2half_rn(0.5f * (__ldg(b_ih + 3 * E + li) + __ldg(b_hh + 3 * E + li))));

    const float* xbase = input + (size_t)warp * TT * IND;

    float4 pf = make_float4(0.f, 0.f, 0.f, 0.f);
    bool ldr = lane < 20;
    int s0 = 0, c0 = 0;
    if (ldr) { int g0 = lane * 4; s0 = g0 / 5; c0 = g0 - s0 * 5; }

    auto stage_chunk = [&](int buf, float4 v) {
        if (ldr) {
            int s = s0, cc = c0;
            float vv[4] = {v.x, v.y, v.z, v.w};
            #pragma unroll
            for (int j = 0; j < 4; j++) {
                xs[wl][buf][s][cc] = __float2half2_rn(vv[j]);   // duplicated
                if (++cc == 5) { cc = 0; s++; }
            }
        }
    };

    if (ldr) pf = *(const float4*)(xbase + lane * 4);
    stage_chunk(0, pf);
    __syncwarp();
    if (ldr) pf = *(const float4*)(xbase + CH * IND + lane * 4);

    float h = 0.0f, c = 0.0f;

    for (int ch = 0; ch < TT / CH; ch++) {
        #pragma unroll
        for (int s = 0; s < CH; s++) {
            __half2* hb = hbuf[wl][s & 1];
            hb[lane] = __float2half2_rn(h);
            __syncwarp();

            uint4 xv[2];
            xv[0] = *(const uint4*)&xs[wl][ch & 1][s][0];
            xv[1] = *(const uint4*)&xs[wl][ch & 1][s][4];
            const __half2* xm = reinterpret_cast<const __half2*>(xv);

            // chains: 0 gets x0,x2,x4; 1 gets x1,x3 with bias init
            __half2 aIF0 = __hmul2(wxIF[0], xm[0]);
            __half2 aIF1 = __hfma2(wxIF[1], xm[1], bIF2);
            __half2 aGO0 = __hmul2(wxGO[0], xm[0]);
            __half2 aGO1 = __hfma2(wxGO[1], xm[1], bGO2);
            aIF0 = __hfma2(wxIF[2], xm[2], aIF0);
            aIF1 = __hfma2(wxIF[3], xm[3], aIF1);
            aGO0 = __hfma2(wxGO[2], xm[2], aGO0);
            aGO1 = __hfma2(wxGO[3], xm[3], aGO1);
            aIF0 = __hfma2(wxIF[4], xm[4], aIF0);
            aGO0 = __hfma2(wxGO[4], xm[4], aGO0);

            // h dot: consume one 16B quarter at a time (low reg pressure)
            #pragma unroll
            for (int q = 0; q < 8; q++) {
                uint4 hv = ((const uint4*)hb)[q];
                const __half2* hm = reinterpret_cast<const __half2*>(&hv);
                #pragma unroll
                for (int j = 0; j < 4; j += 2) {
                    int idx = q * 4 + j;
                    if (idx < E) {
                        aIF0 = __hfma2(whhIF[idx],     hm[j],     aIF0);
                        aIF1 = __hfma2(whhIF[idx + 1], hm[j + 1], aIF1);
                        aGO0 = __hfma2(whhGO[idx],     hm[j],     aGO0);
                        aGO1 = __hfma2(whhGO[idx + 1], hm[j + 1], aGO1);
                    }
                }
            }

            __half2 aIF = __hadd2(aIF0, aIF1);
            __half2 aGO = __hadd2(aGO0, aGO1);

            __half2 tIF = tanh2_fast(aIF);   // (tanh(i/2), tanh(f/2))
            __half2 tGO = tanh2_fast(aGO);   // (tanh(g),   tanh(o/2))

            float ig = fmaf(0.5f, __low2float(tIF), 0.5f);
            float fg = fmaf(0.5f, __high2float(tIF), 0.5f);
            float gg = __low2float(tGO);
            float og = fmaf(0.5f, __high2float(tGO), 0.5f);
            c = fmaf(fg, c, ig * gg);
            h = og * tanh_fast(c);
        }
        if (ch + 1 < TT / CH) {
            stage_chunk((ch + 1) & 1, pf);
            __syncwarp();
            if (ch + 2 < TT / CH && ldr)
                pf = *(const float4*)(xbase + (ch + 2) * CH * IND + lane * 4);
        }
    }

    // ---- fused QKV tail ----
    float aq = __ldg(ipb + 0 * E + li);
    float ak = __ldg(ipb + 1 * E + li);
    float av = __ldg(ipb + 2 * E + li);
    #pragma unroll
    for (int j = 0; j < E; j++) {
        float hj = __shfl_sync(0xffffffffu, h, j);
        float cj = __shfl_sync(0xffffffffu, c, j);
        aq = fmaf(__ldg(ipw + (0 * E + li) * E + j), hj, aq);
        ak = fmaf(__ldg(ipw + (1 * E + li) * E + j), cj, ak);
        av = fmaf(__ldg(ipw + (2 * E + li) * E + j), cj, av);
    }
    if (act) {
        g_hn[(size_t)warp * E + lane] = h;
        g_q[(size_t)warp * E + lane] = aq;
        g_k[(size_t)warp * E + lane] = ak;
        g_v[(size_t)warp * E + lane] = av;
    }
}

// ---------------- kernel 2: attention partials (flash-style, no-max) ----------
// K/V rows padded to 6 u64 (48B): 16B-aligned rows -> 2xLDS.128 + 1xLDS.64.
__global__ __launch_bounds__(ATHR) void attn_kernel()
{
    __shared__ __align__(16) u64 ks2[KTILE * KST];
    __shared__ __align__(16) u64 vs2[KTILE * KST];
    int h   = blockIdx.z;
    int ksp = blockIdx.y;
    int qc  = blockIdx.x;
    int tid = threadIdx.x;
    int k0  = ksp * KTILE;

    for (int i = tid; i < KTILE * 5; i += ATHR) {
        int m = i / 5, p = i - m * 5;
        const float2* kp = (const float2*)(g_k + (size_t)(k0 + m) * E + h * HD) + p;
        const float2* vp = (const float2*)(g_v + (size_t)(k0 + m) * E + h * HD) + p;
        float2 kv = *kp; float2 vv = *vp;
        ks2[m * KST + p] = pack2(kv.x, kv.y);
        vs2[m * KST + p] = pack2(vv.x, vv.y);
    }
    __syncthreads();

    int q0 = qc * (ATHR * RQ) + tid * RQ;
    const float QSC = 0.3162277660168379f * 1.4426950408889634f; // rsqrt(HD)*log2e

    u64 qp[RQ][5], accp[RQ][5];
    float s[RQ];
    #pragma unroll
    for (int r = 0; r < RQ; r++) {
        s[r] = 0.0f;
        #pragma unroll
        for (int p = 0; p < 5; p++) {
            float2 t = *((const float2*)(g_q + (size_t)(q0 + r) * E + h * HD) + p);
            qp[r][p] = pack2(t.x * QSC, t.y * QSC);
            accp[r][p] = pack2(0.0f, 0.0f);
        }
    }

    for (int m = 0; m < KTILE; m++) {
        u64 kk[5], vv[5];
        {
            uint4 a = *(const uint4*)&ks2[m * KST];
            uint4 b = *(const uint4*)&ks2[m * KST + 2];
            kk[0] = ((u64)a.y << 32) | a.x;  kk[1] = ((u64)a.w << 32) | a.z;
            kk[2] = ((u64)b.y << 32) | b.x;  kk[3] = ((u64)b.w << 32) | b.z;
            kk[4] = ks2[m * KST + 4];
            uint4 c2 = *(const uint4*)&vs2[m * KST];
            uint4 d2 = *(const uint4*)&vs2[m * KST + 2];
            vv[0] = ((u64)c2.y << 32) | c2.x;  vv[1] = ((u64)c2.w << 32) | c2.z;
            vv[2] = ((u64)d2.y << 32) | d2.x;  vv[3] = ((u64)d2.w << 32) | d2.z;
            vv[4] = vs2[m * KST + 4];
        }
        #pragma unroll
        for (int r = 0; r < RQ; r++) {
            u64 d2 = pack2(0.0f, 0.0f);
            #pragma unroll
            for (int p = 0; p < 5; p++) d2 = ffma2(qp[r][p], kk[p], d2);
            float lo, hi; unpack2(d2, lo, hi);
            float pr = exp2f(lo + hi);
            s[r] += pr;
            u64 p2 = bcast2(pr);
            #pragma unroll
            for (int p = 0; p < 5; p++) accp[r][p] = ffma2(p2, vv[p], accp[r][p]);
        }
    }

    #pragma unroll
    for (int r = 0; r < RQ; r++) {
        int base = (q0 + r) * (NH * KSPLIT) + h * KSPLIT + ksp;
        g_psum[base] = s[r];
        #pragma unroll
        for (int p = 0; p < 5; p++) {
            float lo, hi; unpack2(accp[r][p], lo, hi);
            g_pacc[(size_t)base * HD + 2 * p]     = lo;
            g_pacc[(size_t)base * HD + 2 * p + 1] = hi;
        }
    }
}

// ---------------- kernel 3: combine + out_proj + LN + MLP + LN + head --------
__global__ __launch_bounds__(256) void epi_kernel(
    const float* __restrict__ opw, const float* __restrict__ opb,
    const float* __restrict__ f1w, const float* __restrict__ f1b,
    const float* __restrict__ f2w, const float* __restrict__ f2b,
    const float* __restrict__ lng, const float* __restrict__ lnb,
    const float* __restrict__ ow,  const float* __restrict__ ob,
    float* __restrict__ out)
{
    int warp = (blockIdx.x * blockDim.x + threadIdx.x) >> 5;
    int lane = threadIdx.x & 31;
    bool act = lane < E;
    int li = act ? lane : 0;
    int hh = li / HD, dd = li - hh * HD;

    // combine split-softmax partials ([q][h][ksp][d]: contiguous per row)
    float num = 0.0f, den = 0.0f;
    #pragma unroll
    for (int ksp = 0; ksp < KSPLIT; ksp++) {
        int base = warp * (NH * KSPLIT) + hh * KSPLIT + ksp;
        num += g_pacc[(size_t)base * HD + dd];
        den += g_psum[base];
    }
    float ctx = __fdividef(num, den);

    // out_proj
    float ao = __ldg(opb + li);
    #pragma unroll
    for (int j = 0; j < E; j++) {
        float cj = __shfl_sync(0xffffffffu, ctx, j);
        ao = fmaf(__ldg(opw + li * E + j), cj, ao);
    }
    float r1 = ao + g_hn[(size_t)warp * E + li];

    // LN1
    float lg = __ldg(lng + li), lb = __ldg(lnb + li);
    float mu = warp_sum(act ? r1 : 0.0f) * (1.0f / E);
    float dv = act ? (r1 - mu) : 0.0f;
    float var = warp_sum(dv * dv) * (1.0f / E);
    float x1 = fmaf(dv * rsqrtf(var + 1e-5f), lg, lb);
    if (!act) x1 = 0.0f;

    // fc1 + exact GELU
    float y = __ldg(f1b + li);
    #pragma unroll
    for (int j = 0; j < E; j++) {
        float xj = __shfl_sync(0xffffffffu, x1, j);
        y = fmaf(__ldg(f1w + li * E + j), xj, y);
    }
    float gy = 0.5f * y * (1.0f + erff(y * 0.7071067811865475f));

    // fc2
    float z = __ldg(f2b + li);
    #pragma unroll
    for (int j = 0; j < E; j++) {
        float gj = __shfl_sync(0xffffffffu, gy, j);
        z = fmaf(__ldg(f2w + li * E + j), gj, z);
    }
    float r2 = x1 + z;

    // LN2
    float mu2 = warp_sum(act ? r2 : 0.0f) * (1.0f / E);
    float dv2 = act ? (r2 - mu2) : 0.0f;
    float var2 = warp_sum(dv2 * dv2) * (1.0f / E);
    float x2 = fmaf(dv2 * rsqrtf(var2 + 1e-5f), lg, lb);
    if (!act) x2 = 0.0f;

    // final head [E -> 3]
    float o0 = __ldg(ob + 0), o1 = __ldg(ob + 1), o2 = __ldg(ob + 2);
    #pragma unroll
    for (int j = 0; j < E; j++) {
        float xj = __shfl_sync(0xffffffffu, x2, j);
        o0 = fmaf(__ldg(ow + 0 * E + j), xj, o0);
        o1 = fmaf(__ldg(ow + 1 * E + j), xj, o1);
        o2 = fmaf(__ldg(ow + 2 * E + j), xj, o2);
    }
    if (lane == 0) {
        out[(size_t)warp * 3 + 0] = o0;
        out[(size_t)warp * 3 + 1] = o1;
        out[(size_t)warp * 3 + 2] = o2;
    }
}

// ---------------- launch ------------------------------------------------------
extern "C" void kernel_launch(void* const* d_in, const int* in_sizes, int n_in,
                              void* d_out, int out_size)
{
    const float* input = (const float*)d_in[0];   // [4096,512,5]
    const float* w_ih  = (const float*)d_in[1];   // [120,5]
    const float* w_hh  = (const float*)d_in[2];   // [120,30]
    const float* b_ih  = (const float*)d_in[3];   // [120]
    const float* b_hh  = (const float*)d_in[4];   // [120]
    const float* ipw   = (const float*)d_in[5];   // [90,30]
    const float* ipb   = (const float*)d_in[6];   // [90]
    const float* opw   = (const float*)d_in[7];   // [30,30]
    const float* opb   = (const float*)d_in[8];   // [30]
    const float* f1w   = (const float*)d_in[9];   // [30,30]
    const float* f1b   = (const float*)d_in[10];  // [30]
    const float* f2w   = (const float*)d_in[11];  // [30,30]
    const float* f2b   = (const float*)d_in[12];  // [30]
    const float* lng   = (const float*)d_in[13];  // [30]
    const float* lnb   = (const float*)d_in[14];  // [30]
    const float* ow    = (const float*)d_in[15];  // [3,30]
    const float* ob    = (const float*)d_in[16];  // [3]
    float* out = (float*)d_out;

    lstm_kernel<<<BB / 4, 128>>>(input, w_ih, w_hh, b_ih, b_hh, ipw, ipb);
    attn_kernel<<<dim3(BB / (ATHR * RQ), KSPLIT, NH), ATHR>>>();
    epi_kernel<<<BB / 8, 256>>>(opw, opb, f1w, f1b, f2w, f2b, lng, lnb, ow, ob, out);
}